// round 10
// baseline (speedup 1.0000x reference)
#include <cuda_runtime.h>
#include <cuda_bf16.h>
#include <cstdint>

#define NN  100000
#define EE  800000
#define DD  96
#define NRD 102   // D + XD

// ---- scratch (device globals; no allocation allowed) ----
__device__ __align__(16) float4 g_num4[NN * 24];
__device__ float  g_den[NN];
__device__ __align__(16) float g_P[NN * DD];
__device__ __align__(16) float g_Q[NN * DD];
__device__ __align__(16) uint4 g_W3hi[96 * 12];     // bf16 [96 o][96 k]
__device__ __align__(16) uint4 g_W3lo[96 * 12];
__device__ __align__(16) uint4 g_W12hi[192 * 16];   // bf16 [192 n][128 k pad]
__device__ __align__(16) uint4 g_W12lo[192 * 16];

__device__ __forceinline__ uint32_t smem_u32(const void* p) {
    uint32_t a;
    asm("{ .reg .u64 t; cvta.to.shared.u64 t, %1; cvt.u32.u64 %0, t; }" : "=r"(a) : "l"(p));
    return a;
}

// ---------------------------------------------------------------------------
// bf16 split helpers
// ---------------------------------------------------------------------------
__device__ __forceinline__ void split4(float4 v, uint2& hi, uint2& lo) {
    uint32_t h01, h23, l01, l23;
    asm("cvt.rn.bf16x2.f32 %0, %1, %2;" : "=r"(h01) : "f"(v.y), "f"(v.x));
    asm("cvt.rn.bf16x2.f32 %0, %1, %2;" : "=r"(h23) : "f"(v.w), "f"(v.z));
    float r0 = v.x - __uint_as_float(h01 << 16);
    float r1 = v.y - __uint_as_float(h01 & 0xFFFF0000u);
    float r2 = v.z - __uint_as_float(h23 << 16);
    float r3 = v.w - __uint_as_float(h23 & 0xFFFF0000u);
    asm("cvt.rn.bf16x2.f32 %0, %1, %2;" : "=r"(l01) : "f"(r1), "f"(r0));
    asm("cvt.rn.bf16x2.f32 %0, %1, %2;" : "=r"(l23) : "f"(r3), "f"(r2));
    hi = make_uint2(h01, h23); lo = make_uint2(l01, l23);
}
__device__ __forceinline__ void split2(float f0, float f1, uint32_t& hi, uint32_t& lo) {
    asm("cvt.rn.bf16x2.f32 %0, %1, %2;" : "=r"(hi) : "f"(f1), "f"(f0));
    float r0 = f0 - __uint_as_float(hi << 16);
    float r1 = f1 - __uint_as_float(hi & 0xFFFF0000u);
    asm("cvt.rn.bf16x2.f32 %0, %1, %2;" : "=r"(lo) : "f"(r1), "f"(r0));
}

// ---------------------------------------------------------------------------
// K0: zero accumulators, write x cols; block 0 pre-splits W3 and W1|W2
// ---------------------------------------------------------------------------
__global__ void init_k(const float* __restrict__ x, float* __restrict__ node_out,
                       const float* __restrict__ W) {
    if (blockIdx.x == 0) {
        for (int i = threadIdx.x; i < 96 * 24; i += 256) {
            int o = i / 24, q = i % 24;
            float4 v = *(const float4*)(W + o * 300 + 204 + q * 4);
            uint2 hi, lo;
            split4(v, hi, lo);
            *((uint2*)g_W3hi + o * 24 + q) = hi;
            *((uint2*)g_W3lo + o * 24 + q) = lo;
        }
        for (int i = threadIdx.x; i < 192 * 64; i += 256) {
            int n = i >> 6, kp = i & 63, k = kp * 2;
            const float* src = (n < 96) ? (W + n * 300 + k) : (W + (n - 96) * 300 + 102 + k);
            float f0 = (k < 102) ? src[0] : 0.f;
            float f1 = (k + 1 < 102) ? src[1] : 0.f;
            uint32_t hi, lo;
            split2(f0, f1, hi, lo);
            ((uint32_t*)g_W12hi)[i] = hi;
            ((uint32_t*)g_W12lo)[i] = lo;
        }
    }
    int i = blockIdx.x * 256 + threadIdx.x;
    if (i < NN * 24) g_num4[i] = make_float4(0.f, 0.f, 0.f, 0.f);
    if (i < NN)      g_den[i] = 0.f;
    if (i < NN * 6)  node_out[(i / 6) * NRD + 96 + (i % 6)] = x[i];
}

// ---------------------------------------------------------------------------
// K1: masked scatter-sum — ONE THREAD PER EDGE, batched MLP=8 loads + REDG.
// ---------------------------------------------------------------------------
__global__ void scatter_k(const int* __restrict__ ei,
                          const float* __restrict__ attr,
                          const float* __restrict__ mask) {
    int e = blockIdx.x * 256 + threadIdx.x;
    if (e >= EE) return;
    int c = ei[EE + e];
    float m = mask[e];
    atomicAdd(&g_den[c], m);
    const float4* src = (const float4*)(attr + (size_t)e * 96);
    float* dst = ((float*)g_num4) + (size_t)c * 96;
    #pragma unroll
    for (int q0 = 0; q0 < 24; q0 += 8) {
        float4 v[8];
        #pragma unroll
        for (int j = 0; j < 8; j++) v[j] = src[q0 + j];
        #pragma unroll
        for (int j = 0; j < 8; j++) {
            asm volatile("red.global.add.v4.f32 [%0], {%1,%2,%3,%4};"
                         :: "l"(dst + (size_t)(q0 + j) * 4),
                            "f"(v[j].x * m), "f"(v[j].y * m),
                            "f"(v[j].z * m), "f"(v[j].w * m)
                         : "memory");
        }
    }
}

// ---------------------------------------------------------------------------
__global__ void finalize_k(float* __restrict__ node_out) {
    int i = blockIdx.x * 256 + threadIdx.x;
    if (i >= NN * 24) return;
    int n = i / 24;
    int q = i - n * 24;
    float inv = 1.f / (g_den[n] + 1.f);
    float4 v = g_num4[i];
    float* dst = node_out + (size_t)n * NRD + q * 4;
    dst[0] = v.x * inv; dst[1] = v.y * inv; dst[2] = v.z * inv; dst[3] = v.w * inv;
}

// ---------------------------------------------------------------------------
__global__ void blend_k(const int* __restrict__ change,
                        const int* __restrict__ is_support,
                        const int* __restrict__ tails,
                        const float* __restrict__ support_tail,
                        float* __restrict__ node_out) {
    if (change[0] == 0) return;
    const int TOT = 128 * NRD;
    int tid = threadIdx.x;
    float vals[13];
    int   addr[13];
    short dim[13];
    int cnt = 0;
    for (int i = tid; i < TOT; i += 1024) {
        int t = i / NRD, d = i - t * NRD;
        int node = tails[t];
        addr[cnt] = node * NRD + d;
        dim[cnt]  = (short)d;
        vals[cnt] = node_out[addr[cnt]];
        cnt++;
    }
    if (is_support[0]) {
        __shared__ float ssum[NRD];
        for (int d = tid; d < NRD; d += 1024) ssum[d] = 0.f;
        __syncthreads();
        for (int j = 0; j < cnt; j++) atomicAdd(&ssum[dim[j]], vals[j]);
        __syncthreads();
        for (int j = 0; j < cnt; j++)
            node_out[addr[j]] = ssum[dim[j]] * (1.f / 128.f);
    } else {
        __syncthreads();
        for (int j = 0; j < cnt; j++)
            node_out[addr[j]] = 0.1f * support_tail[dim[j]] + 0.9f * vals[j];
    }
}

// ---------------------------------------------------------------------------
// shared MMA helpers
// ---------------------------------------------------------------------------
__device__ __forceinline__ void ldsm4(uint32_t addr, uint32_t* r) {
    asm volatile("ldmatrix.sync.aligned.m8n8.x4.shared.b16 {%0,%1,%2,%3}, [%4];"
                 : "=r"(r[0]), "=r"(r[1]), "=r"(r[2]), "=r"(r[3]) : "r"(addr));
}
__device__ __forceinline__ void mma_bf16(float4& c, const uint32_t* a,
                                         uint32_t b0, uint32_t b1) {
    asm volatile(
        "mma.sync.aligned.m16n8k16.row.col.f32.bf16.bf16.f32 "
        "{%0,%1,%2,%3}, {%4,%5,%6,%7}, {%8,%9}, {%0,%1,%2,%3};"
        : "+f"(c.x), "+f"(c.y), "+f"(c.z), "+f"(c.w)
        : "r"(a[0]), "r"(a[1]), "r"(a[2]), "r"(a[3]), "r"(b0), "r"(b1));
}

#define RS 80           // row stride bytes (64B data + 16B pad)

// ---------------------------------------------------------------------------
// K4: P|Q fused GEMM via HMMA bf16 3-term split (R8 version, proven)
// ---------------------------------------------------------------------------
__global__ __launch_bounds__(256, 2) void pq_mma(const float* __restrict__ node_rep) {
    __shared__ __align__(16) char sAhi[64 * RS];
    __shared__ __align__(16) char sAlo[64 * RS];
    __shared__ __align__(16) char sBhi[192 * RS];
    __shared__ __align__(16) char sBlo[192 * RS];

    int tid = threadIdx.x, lane = tid & 31, w = tid >> 5;
    int n0 = blockIdx.x * 64;
    int w4 = w & 3, nh = w >> 2;

    uint32_t aHi = smem_u32(sAhi), aLo = smem_u32(sAlo);
    uint32_t bHi = smem_u32(sBhi), bLo = smem_u32(sBlo);

    uint32_t aoff = (uint32_t)(w4 * 16 + (lane & 15)) * RS + ((lane >> 4) & 1) * 16;
    uint32_t boff = ((lane >> 4) & 1) * 8 * RS + (uint32_t)(lane & 7) * RS
                  + ((lane >> 3) & 1) * 16;

    float4 acc[12];
    #pragma unroll
    for (int t = 0; t < 12; t++) acc[t] = make_float4(0.f, 0.f, 0.f, 0.f);

    #pragma unroll
    for (int c = 0; c < 4; c++) {
        int kc0 = c * 32;
        if (c) __syncthreads();
        #pragma unroll
        for (int v = 0; v < 4; v++) {
            int f = tid + v * 256;
            int r = f >> 4, j = f & 15;
            int k = kc0 + j * 2;
            int n = n0 + r;
            float2 val = (n < NN && k < 102)
                ? *(const float2*)(node_rep + (size_t)n * NRD + k)
                : make_float2(0.f, 0.f);
            uint32_t hi, lo;
            split2(val.x, val.y, hi, lo);
            int off = r * RS + j * 4;
            *(uint32_t*)(sAhi + off) = hi;
            *(uint32_t*)(sAlo + off) = lo;
        }
        #pragma unroll
        for (int v = 0; v < 6; v++) {
            int f = tid + v * 256;
            int sel = f >= 768;
            int g = sel ? f - 768 : f;
            int o = g >> 2, q = g & 3;
            uint4 val = (sel ? g_W12lo : g_W12hi)[o * 16 + c * 4 + q];
            *(uint4*)((sel ? sBlo : sBhi) + o * RS + q * 16) = val;
        }
        __syncthreads();

        #pragma unroll
        for (int kc16 = 0; kc16 < 2; kc16++) {
            uint32_t ah[4], al[4];
            ldsm4(aHi + aoff + kc16 * 32, ah);
            ldsm4(aLo + aoff + kc16 * 32, al);
            #pragma unroll
            for (int tp = 0; tp < 6; tp++) {
                uint32_t bh[4], bl[4];
                uint32_t bo = (uint32_t)(nh * 96 + tp * 16) * RS + boff + kc16 * 32;
                ldsm4(bHi + bo, bh);
                ldsm4(bLo + bo, bl);
                mma_bf16(acc[tp * 2],     ah, bh[0], bh[1]);
                mma_bf16(acc[tp * 2],     ah, bl[0], bl[1]);
                mma_bf16(acc[tp * 2],     al, bh[0], bh[1]);
                mma_bf16(acc[tp * 2 + 1], ah, bh[2], bh[3]);
                mma_bf16(acc[tp * 2 + 1], ah, bl[2], bl[3]);
                mma_bf16(acc[tp * 2 + 1], al, bh[2], bh[3]);
            }
        }
    }

    float* outb = nh ? g_Q : g_P;
    int mrow = w4 * 16 + (lane >> 2);
    int kq = lane & 3;
    int node0 = n0 + mrow, node1 = node0 + 8;
    #pragma unroll
    for (int t = 0; t < 12; t++) {
        int col = t * 8 + kq * 2;
        if (node0 < NN)
            *(float2*)(outb + (size_t)node0 * 96 + col) = make_float2(acc[t].x, acc[t].y);
        if (node1 < NN)
            *(float2*)(outb + (size_t)node1 * 96 + col) = make_float2(acc[t].z, acc[t].w);
    }
}

// ---------------------------------------------------------------------------
// K5: edge_rep HMMA — R8 chunked + register prefetch + direct epilogue.
// ---------------------------------------------------------------------------
__global__ __launch_bounds__(256, 2) void edge_mma(const float* __restrict__ attr,
                                                   const float* __restrict__ b,
                                                   const int* __restrict__ ei,
                                                   float* __restrict__ out) {
    __shared__ __align__(16) char sAhi[128 * RS];   // 10240 B
    __shared__ __align__(16) char sAlo[128 * RS];
    __shared__ __align__(16) char sBhi[96 * RS];    //  7680 B
    __shared__ __align__(16) char sBlo[96 * RS];

    int tid = threadIdx.x, lane = tid & 31, w = tid >> 5;
    size_t e0 = (size_t)blockIdx.x * 128;

    uint32_t aHi = smem_u32(sAhi), aLo = smem_u32(sAlo);
    uint32_t bHi = smem_u32(sBhi), bLo = smem_u32(sBlo);

    uint32_t aoff = (uint32_t)(w * 16 + (lane & 15)) * RS + ((lane >> 4) & 1) * 16;
    uint32_t boff = ((lane >> 4) & 1) * 8 * RS + (uint32_t)(lane & 7) * RS
                  + ((lane >> 3) & 1) * 16;

    float4 acc[12];
    #pragma unroll
    for (int t = 0; t < 12; t++) acc[t] = make_float4(0.f, 0.f, 0.f, 0.f);

    float4 pa[4];
    uint4  pb[3];

    #pragma unroll
    for (int v = 0; v < 4; v++) {
        int f = tid + v * 256;
        int r = f >> 3, q4 = f & 7;
        pa[v] = *(const float4*)(attr + (e0 + r) * 96 + q4 * 4);
    }
    #pragma unroll
    for (int v = 0; v < 3; v++) {
        int f = tid + v * 256;
        int sel = f >= 384;
        int g = sel ? f - 384 : f;
        pb[v] = (sel ? g_W3lo : g_W3hi)[(g >> 2) * 12 + (g & 3)];
    }

    #pragma unroll
    for (int c = 0; c < 3; c++) {
        if (c) __syncthreads();
        #pragma unroll
        for (int v = 0; v < 4; v++) {
            int f = tid + v * 256;
            int r = f >> 3, q4 = f & 7;
            uint2 hi, lo;
            split4(pa[v], hi, lo);
            int off = r * RS + q4 * 8;
            *(uint2*)(sAhi + off) = hi;
            *(uint2*)(sAlo + off) = lo;
        }
        #pragma unroll
        for (int v = 0; v < 3; v++) {
            int f = tid + v * 256;
            int sel = f >= 384;
            int g = sel ? f - 384 : f;
            *(uint4*)((sel ? sBlo : sBhi) + (g >> 2) * RS + (g & 3) * 16) = pb[v];
        }
        __syncthreads();
        if (c < 2) {
            int kc0 = (c + 1) * 32;
            int kqo = kc0 >> 3;
            #pragma unroll
            for (int v = 0; v < 4; v++) {
                int f = tid + v * 256;
                int r = f >> 3, q4 = f & 7;
                pa[v] = *(const float4*)(attr + (e0 + r) * 96 + kc0 + q4 * 4);
            }
            #pragma unroll
            for (int v = 0; v < 3; v++) {
                int f = tid + v * 256;
                int sel = f >= 384;
                int g = sel ? f - 384 : f;
                pb[v] = (sel ? g_W3lo : g_W3hi)[(g >> 2) * 12 + kqo + (g & 3)];
            }
        }
        #pragma unroll
        for (int kc16 = 0; kc16 < 2; kc16++) {
            uint32_t ah[4], al[4];
            ldsm4(aHi + aoff + kc16 * 32, ah);
            ldsm4(aLo + aoff + kc16 * 32, al);
            #pragma unroll
            for (int tp = 0; tp < 6; tp++) {
                uint32_t bh[4], bl[4];
                uint32_t bo = (uint32_t)(tp * 16) * RS + boff + kc16 * 32;
                ldsm4(bHi + bo, bh);
                ldsm4(bLo + bo, bl);
                mma_bf16(acc[tp * 2],     ah, bh[0], bh[1]);
                mma_bf16(acc[tp * 2],     ah, bl[0], bl[1]);
                mma_bf16(acc[tp * 2],     al, bh[0], bh[1]);
                mma_bf16(acc[tp * 2 + 1], ah, bh[2], bh[3]);
                mma_bf16(acc[tp * 2 + 1], ah, bl[2], bl[3]);
                mma_bf16(acc[tp * 2 + 1], al, bh[2], bh[3]);
            }
        }
    }

    // epilogue (R8 direct form)
    int mrow = w * 16 + (lane >> 2);
    int kq = lane & 3;
    int er0 = (int)e0 + mrow;
    int er1 = er0 + 8;
    int r0i = ei[er0], c0i = ei[EE + er0];
    int r1i = ei[er1], c1i = ei[EE + er1];
    const float* P0 = g_P + (size_t)r0i * 96;
    const float* Q0 = g_Q + (size_t)c0i * 96;
    const float* P1 = g_P + (size_t)r1i * 96;
    const float* Q1 = g_Q + (size_t)c1i * 96;
    float* o0 = out + (size_t)er0 * 96;
    float* o1 = out + (size_t)er1 * 96;
    #pragma unroll
    for (int t = 0; t < 12; t++) {
        int col = t * 8 + kq * 2;
        float2 bv = *(const float2*)(b + col);
        float2 p0 = *(const float2*)(P0 + col), q0 = *(const float2*)(Q0 + col);
        *(float2*)(o0 + col) = make_float2(acc[t].x + p0.x + q0.x + bv.x,
                                           acc[t].y + p0.y + q0.y + bv.y);
        float2 p1 = *(const float2*)(P1 + col), q1 = *(const float2*)(Q1 + col);
        *(float2*)(o1 + col) = make_float2(acc[t].z + p1.x + q1.x + bv.x,
                                           acc[t].w + p1.y + q1.y + bv.y);
    }
}

// ---------------------------------------------------------------------------
extern "C" void kernel_launch(void* const* d_in, const int* in_sizes, int n_in,
                              void* d_out, int out_size) {
    const int*   change = (const int*)d_in[0];
    const int*   is_sup = (const int*)d_in[1];
    const int*   tails  = (const int*)d_in[3];
    const float* x      = (const float*)d_in[4];
    const int*   ei     = (const int*)d_in[5];
    const float* attr   = (const float*)d_in[6];
    const float* mask   = (const float*)d_in[7];
    const float* stail  = (const float*)d_in[9];
    const float* W      = (const float*)d_in[10];
    const float* b      = (const float*)d_in[11];

    float* node_out = (float*)d_out;
    float* edge_out = node_out + (size_t)NN * NRD;

    init_k    <<<(NN * 24 + 255) / 256, 256>>>(x, node_out, W);
    scatter_k <<<(EE + 255) / 256, 256>>>(ei, attr, mask);
    finalize_k<<<(NN * 24 + 255) / 256, 256>>>(node_out);
    blend_k   <<<1, 1024>>>(change, is_sup, tails, stail, node_out);
    pq_mma    <<<(NN + 63) / 64, 256>>>(node_out);
    edge_mma  <<<EE / 128, 256>>>(attr, b, ei, edge_out);
}

// round 11
// speedup vs baseline: 1.1426x; 1.1426x over previous
#include <cuda_runtime.h>
#include <cuda_bf16.h>
#include <cstdint>

#define NN  100000
#define EE  800000
#define DD  96
#define NRD 102   // D + XD

// ---- scratch (device globals; no allocation allowed) ----
__device__ __align__(16) float4 g_num4[NN * 24];
__device__ float  g_den[NN];
__device__ __align__(16) float g_P[NN * DD];
__device__ __align__(16) float g_Q[NN * DD];
__device__ __align__(16) uint4 g_W3hi[96 * 12];     // bf16 [96 o][96 k]
__device__ __align__(16) uint4 g_W3lo[96 * 12];
__device__ __align__(16) uint4 g_W12hi[192 * 16];   // bf16 [192 n][128 k pad]
__device__ __align__(16) uint4 g_W12lo[192 * 16];

__device__ __forceinline__ uint32_t smem_u32(const void* p) {
    uint32_t a;
    asm("{ .reg .u64 t; cvta.to.shared.u64 t, %1; cvt.u32.u64 %0, t; }" : "=r"(a) : "l"(p));
    return a;
}

// ---------------------------------------------------------------------------
// bf16 split helpers
// ---------------------------------------------------------------------------
__device__ __forceinline__ void split4(float4 v, uint2& hi, uint2& lo) {
    uint32_t h01, h23, l01, l23;
    asm("cvt.rn.bf16x2.f32 %0, %1, %2;" : "=r"(h01) : "f"(v.y), "f"(v.x));
    asm("cvt.rn.bf16x2.f32 %0, %1, %2;" : "=r"(h23) : "f"(v.w), "f"(v.z));
    float r0 = v.x - __uint_as_float(h01 << 16);
    float r1 = v.y - __uint_as_float(h01 & 0xFFFF0000u);
    float r2 = v.z - __uint_as_float(h23 << 16);
    float r3 = v.w - __uint_as_float(h23 & 0xFFFF0000u);
    asm("cvt.rn.bf16x2.f32 %0, %1, %2;" : "=r"(l01) : "f"(r1), "f"(r0));
    asm("cvt.rn.bf16x2.f32 %0, %1, %2;" : "=r"(l23) : "f"(r3), "f"(r2));
    hi = make_uint2(h01, h23); lo = make_uint2(l01, l23);
}
__device__ __forceinline__ void split2(float f0, float f1, uint32_t& hi, uint32_t& lo) {
    asm("cvt.rn.bf16x2.f32 %0, %1, %2;" : "=r"(hi) : "f"(f1), "f"(f0));
    float r0 = f0 - __uint_as_float(hi << 16);
    float r1 = f1 - __uint_as_float(hi & 0xFFFF0000u);
    asm("cvt.rn.bf16x2.f32 %0, %1, %2;" : "=r"(lo) : "f"(r1), "f"(r0));
}

// ---------------------------------------------------------------------------
// K0: zero accumulators, write x cols; block 0 pre-splits W3 and W1|W2
// ---------------------------------------------------------------------------
__global__ void init_k(const float* __restrict__ x, float* __restrict__ node_out,
                       const float* __restrict__ W) {
    if (blockIdx.x == 0) {
        for (int i = threadIdx.x; i < 96 * 24; i += 256) {
            int o = i / 24, q = i % 24;
            float4 v = *(const float4*)(W + o * 300 + 204 + q * 4);
            uint2 hi, lo;
            split4(v, hi, lo);
            *((uint2*)g_W3hi + o * 24 + q) = hi;
            *((uint2*)g_W3lo + o * 24 + q) = lo;
        }
        for (int i = threadIdx.x; i < 192 * 64; i += 256) {
            int n = i >> 6, kp = i & 63, k = kp * 2;
            const float* src = (n < 96) ? (W + n * 300 + k) : (W + (n - 96) * 300 + 102 + k);
            float f0 = (k < 102) ? src[0] : 0.f;
            float f1 = (k + 1 < 102) ? src[1] : 0.f;
            uint32_t hi, lo;
            split2(f0, f1, hi, lo);
            ((uint32_t*)g_W12hi)[i] = hi;
            ((uint32_t*)g_W12lo)[i] = lo;
        }
    }
    int i = blockIdx.x * 256 + threadIdx.x;
    if (i < NN * 24) g_num4[i] = make_float4(0.f, 0.f, 0.f, 0.f);
    if (i < NN)      g_den[i] = 0.f;
    if (i < NN * 6)  node_out[(i / 6) * NRD + 96 + (i % 6)] = x[i];
}

// ---------------------------------------------------------------------------
// K1: masked scatter-sum — R8 proven form: one thread per (edge, quad)
// ---------------------------------------------------------------------------
__global__ void scatter_k(const int* __restrict__ ei,
                          const float* __restrict__ attr,
                          const float* __restrict__ mask) {
    int i = blockIdx.x * 256 + threadIdx.x;
    if (i >= EE * 24) return;
    int e = i / 24;
    int q = i - e * 24;
    int c = ei[EE + e];
    float m = mask[e];
    float4 v = *(const float4*)(attr + (size_t)e * 96 + q * 4);
    float* dst = ((float*)g_num4) + (size_t)c * 96 + q * 4;
    asm volatile("red.global.add.v4.f32 [%0], {%1,%2,%3,%4};"
                 :: "l"(dst), "f"(v.x * m), "f"(v.y * m), "f"(v.z * m), "f"(v.w * m)
                 : "memory");
    if (q == 0) atomicAdd(&g_den[c], m);
}

// ---------------------------------------------------------------------------
__global__ void finalize_k(float* __restrict__ node_out) {
    int i = blockIdx.x * 256 + threadIdx.x;
    if (i >= NN * 24) return;
    int n = i / 24;
    int q = i - n * 24;
    float inv = 1.f / (g_den[n] + 1.f);
    float4 v = g_num4[i];
    float* dst = node_out + (size_t)n * NRD + q * 4;
    dst[0] = v.x * inv; dst[1] = v.y * inv; dst[2] = v.z * inv; dst[3] = v.w * inv;
}

// ---------------------------------------------------------------------------
__global__ void blend_k(const int* __restrict__ change,
                        const int* __restrict__ is_support,
                        const int* __restrict__ tails,
                        const float* __restrict__ support_tail,
                        float* __restrict__ node_out) {
    if (change[0] == 0) return;
    const int TOT = 128 * NRD;
    int tid = threadIdx.x;
    float vals[13];
    int   addr[13];
    short dim[13];
    int cnt = 0;
    for (int i = tid; i < TOT; i += 1024) {
        int t = i / NRD, d = i - t * NRD;
        int node = tails[t];
        addr[cnt] = node * NRD + d;
        dim[cnt]  = (short)d;
        vals[cnt] = node_out[addr[cnt]];
        cnt++;
    }
    if (is_support[0]) {
        __shared__ float ssum[NRD];
        for (int d = tid; d < NRD; d += 1024) ssum[d] = 0.f;
        __syncthreads();
        for (int j = 0; j < cnt; j++) atomicAdd(&ssum[dim[j]], vals[j]);
        __syncthreads();
        for (int j = 0; j < cnt; j++)
            node_out[addr[j]] = ssum[dim[j]] * (1.f / 128.f);
    } else {
        __syncthreads();
        for (int j = 0; j < cnt; j++)
            node_out[addr[j]] = 0.1f * support_tail[dim[j]] + 0.9f * vals[j];
    }
}

// ---------------------------------------------------------------------------
// shared MMA helpers
// ---------------------------------------------------------------------------
__device__ __forceinline__ void ldsm4(uint32_t addr, uint32_t* r) {
    asm volatile("ldmatrix.sync.aligned.m8n8.x4.shared.b16 {%0,%1,%2,%3}, [%4];"
                 : "=r"(r[0]), "=r"(r[1]), "=r"(r[2]), "=r"(r[3]) : "r"(addr));
}
__device__ __forceinline__ void mma_bf16(float4& c, const uint32_t* a,
                                         uint32_t b0, uint32_t b1) {
    asm volatile(
        "mma.sync.aligned.m16n8k16.row.col.f32.bf16.bf16.f32 "
        "{%0,%1,%2,%3}, {%4,%5,%6,%7}, {%8,%9}, {%0,%1,%2,%3};"
        : "+f"(c.x), "+f"(c.y), "+f"(c.z), "+f"(c.w)
        : "r"(a[0]), "r"(a[1]), "r"(a[2]), "r"(a[3]), "r"(b0), "r"(b1));
}

#define RS 80           // row stride bytes (64B data + 16B pad)

// ---------------------------------------------------------------------------
// K4: P|Q fused GEMM via HMMA bf16 3-term split (R8 version, proven)
// ---------------------------------------------------------------------------
__global__ __launch_bounds__(256, 2) void pq_mma(const float* __restrict__ node_rep) {
    __shared__ __align__(16) char sAhi[64 * RS];
    __shared__ __align__(16) char sAlo[64 * RS];
    __shared__ __align__(16) char sBhi[192 * RS];
    __shared__ __align__(16) char sBlo[192 * RS];

    int tid = threadIdx.x, lane = tid & 31, w = tid >> 5;
    int n0 = blockIdx.x * 64;
    int w4 = w & 3, nh = w >> 2;

    uint32_t aHi = smem_u32(sAhi), aLo = smem_u32(sAlo);
    uint32_t bHi = smem_u32(sBhi), bLo = smem_u32(sBlo);

    uint32_t aoff = (uint32_t)(w4 * 16 + (lane & 15)) * RS + ((lane >> 4) & 1) * 16;
    uint32_t boff = ((lane >> 4) & 1) * 8 * RS + (uint32_t)(lane & 7) * RS
                  + ((lane >> 3) & 1) * 16;

    float4 acc[12];
    #pragma unroll
    for (int t = 0; t < 12; t++) acc[t] = make_float4(0.f, 0.f, 0.f, 0.f);

    #pragma unroll
    for (int c = 0; c < 4; c++) {
        int kc0 = c * 32;
        if (c) __syncthreads();
        #pragma unroll
        for (int v = 0; v < 4; v++) {
            int f = tid + v * 256;
            int r = f >> 4, j = f & 15;
            int k = kc0 + j * 2;
            int n = n0 + r;
            float2 val = (n < NN && k < 102)
                ? *(const float2*)(node_rep + (size_t)n * NRD + k)
                : make_float2(0.f, 0.f);
            uint32_t hi, lo;
            split2(val.x, val.y, hi, lo);
            int off = r * RS + j * 4;
            *(uint32_t*)(sAhi + off) = hi;
            *(uint32_t*)(sAlo + off) = lo;
        }
        #pragma unroll
        for (int v = 0; v < 6; v++) {
            int f = tid + v * 256;
            int sel = f >= 768;
            int g = sel ? f - 768 : f;
            int o = g >> 2, q = g & 3;
            uint4 val = (sel ? g_W12lo : g_W12hi)[o * 16 + c * 4 + q];
            *(uint4*)((sel ? sBlo : sBhi) + o * RS + q * 16) = val;
        }
        __syncthreads();

        #pragma unroll
        for (int kc16 = 0; kc16 < 2; kc16++) {
            uint32_t ah[4], al[4];
            ldsm4(aHi + aoff + kc16 * 32, ah);
            ldsm4(aLo + aoff + kc16 * 32, al);
            #pragma unroll
            for (int tp = 0; tp < 6; tp++) {
                uint32_t bh[4], bl[4];
                uint32_t bo = (uint32_t)(nh * 96 + tp * 16) * RS + boff + kc16 * 32;
                ldsm4(bHi + bo, bh);
                ldsm4(bLo + bo, bl);
                mma_bf16(acc[tp * 2],     ah, bh[0], bh[1]);
                mma_bf16(acc[tp * 2],     ah, bl[0], bl[1]);
                mma_bf16(acc[tp * 2],     al, bh[0], bh[1]);
                mma_bf16(acc[tp * 2 + 1], ah, bh[2], bh[3]);
                mma_bf16(acc[tp * 2 + 1], ah, bl[2], bl[3]);
                mma_bf16(acc[tp * 2 + 1], al, bh[2], bh[3]);
            }
        }
    }

    float* outb = nh ? g_Q : g_P;
    int mrow = w4 * 16 + (lane >> 2);
    int kq = lane & 3;
    int node0 = n0 + mrow, node1 = node0 + 8;
    #pragma unroll
    for (int t = 0; t < 12; t++) {
        int col = t * 8 + kq * 2;
        if (node0 < NN)
            *(float2*)(outb + (size_t)node0 * 96 + col) = make_float2(acc[t].x, acc[t].y);
        if (node1 < NN)
            *(float2*)(outb + (size_t)node1 * 96 + col) = make_float2(acc[t].z, acc[t].w);
    }
}

// ---------------------------------------------------------------------------
// K5: edge_rep HMMA — R8 chunked + register prefetch + direct epilogue,
//     with ei loads hoisted to kernel start and P/Q rows prefetched into L1.
// ---------------------------------------------------------------------------
__global__ __launch_bounds__(256, 2) void edge_mma(const float* __restrict__ attr,
                                                   const float* __restrict__ b,
                                                   const int* __restrict__ ei,
                                                   float* __restrict__ out) {
    __shared__ __align__(16) char sAhi[128 * RS];   // 10240 B
    __shared__ __align__(16) char sAlo[128 * RS];
    __shared__ __align__(16) char sBhi[96 * RS];    //  7680 B
    __shared__ __align__(16) char sBlo[96 * RS];

    int tid = threadIdx.x, lane = tid & 31, w = tid >> 5;
    size_t e0 = (size_t)blockIdx.x * 128;

    // hoisted epilogue indices + L1 prefetch of P/Q rows
    int mrow = w * 16 + (lane >> 2);
    int kq = lane & 3;
    int er0 = (int)e0 + mrow;
    int er1 = er0 + 8;
    int r0i = ei[er0], c0i = ei[EE + er0];
    int r1i = ei[er1], c1i = ei[EE + er1];
    if (kq < 3) {
        int lo = kq * 32;
        asm volatile("prefetch.global.L1 [%0];" :: "l"(g_P + (size_t)r0i * 96 + lo));
        asm volatile("prefetch.global.L1 [%0];" :: "l"(g_Q + (size_t)c0i * 96 + lo));
        asm volatile("prefetch.global.L1 [%0];" :: "l"(g_P + (size_t)r1i * 96 + lo));
        asm volatile("prefetch.global.L1 [%0];" :: "l"(g_Q + (size_t)c1i * 96 + lo));
    }

    uint32_t aHi = smem_u32(sAhi), aLo = smem_u32(sAlo);
    uint32_t bHi = smem_u32(sBhi), bLo = smem_u32(sBlo);

    uint32_t aoff = (uint32_t)(w * 16 + (lane & 15)) * RS + ((lane >> 4) & 1) * 16;
    uint32_t boff = ((lane >> 4) & 1) * 8 * RS + (uint32_t)(lane & 7) * RS
                  + ((lane >> 3) & 1) * 16;

    float4 acc[12];
    #pragma unroll
    for (int t = 0; t < 12; t++) acc[t] = make_float4(0.f, 0.f, 0.f, 0.f);

    float4 pa[4];
    uint4  pb[3];

    #pragma unroll
    for (int v = 0; v < 4; v++) {
        int f = tid + v * 256;
        int r = f >> 3, q4 = f & 7;
        pa[v] = *(const float4*)(attr + (e0 + r) * 96 + q4 * 4);
    }
    #pragma unroll
    for (int v = 0; v < 3; v++) {
        int f = tid + v * 256;
        int sel = f >= 384;
        int g = sel ? f - 384 : f;
        pb[v] = (sel ? g_W3lo : g_W3hi)[(g >> 2) * 12 + (g & 3)];
    }

    #pragma unroll
    for (int c = 0; c < 3; c++) {
        if (c) __syncthreads();
        #pragma unroll
        for (int v = 0; v < 4; v++) {
            int f = tid + v * 256;
            int r = f >> 3, q4 = f & 7;
            uint2 hi, lo;
            split4(pa[v], hi, lo);
            int off = r * RS + q4 * 8;
            *(uint2*)(sAhi + off) = hi;
            *(uint2*)(sAlo + off) = lo;
        }
        #pragma unroll
        for (int v = 0; v < 3; v++) {
            int f = tid + v * 256;
            int sel = f >= 384;
            int g = sel ? f - 384 : f;
            *(uint4*)((sel ? sBlo : sBhi) + (g >> 2) * RS + (g & 3) * 16) = pb[v];
        }
        __syncthreads();
        if (c < 2) {
            int kc0 = (c + 1) * 32;
            int kqo = kc0 >> 3;
            #pragma unroll
            for (int v = 0; v < 4; v++) {
                int f = tid + v * 256;
                int r = f >> 3, q4 = f & 7;
                pa[v] = *(const float4*)(attr + (e0 + r) * 96 + kc0 + q4 * 4);
            }
            #pragma unroll
            for (int v = 0; v < 3; v++) {
                int f = tid + v * 256;
                int sel = f >= 384;
                int g = sel ? f - 384 : f;
                pb[v] = (sel ? g_W3lo : g_W3hi)[(g >> 2) * 12 + kqo + (g & 3)];
            }
        }
        #pragma unroll
        for (int kc16 = 0; kc16 < 2; kc16++) {
            uint32_t ah[4], al[4];
            ldsm4(aHi + aoff + kc16 * 32, ah);
            ldsm4(aLo + aoff + kc16 * 32, al);
            #pragma unroll
            for (int tp = 0; tp < 6; tp++) {
                uint32_t bh[4], bl[4];
                uint32_t bo = (uint32_t)(tp * 16) * RS + boff + kc16 * 32;
                ldsm4(bHi + bo, bh);
                ldsm4(bLo + bo, bl);
                mma_bf16(acc[tp * 2],     ah, bh[0], bh[1]);
                mma_bf16(acc[tp * 2],     ah, bl[0], bl[1]);
                mma_bf16(acc[tp * 2],     al, bh[0], bh[1]);
                mma_bf16(acc[tp * 2 + 1], ah, bh[2], bh[3]);
                mma_bf16(acc[tp * 2 + 1], ah, bl[2], bl[3]);
                mma_bf16(acc[tp * 2 + 1], al, bh[2], bh[3]);
            }
        }
    }

    // epilogue (R8 direct form, indices already in registers)
    const float* P0 = g_P + (size_t)r0i * 96;
    const float* Q0 = g_Q + (size_t)c0i * 96;
    const float* P1 = g_P + (size_t)r1i * 96;
    const float* Q1 = g_Q + (size_t)c1i * 96;
    float* o0 = out + (size_t)er0 * 96;
    float* o1 = out + (size_t)er1 * 96;
    #pragma unroll
    for (int t = 0; t < 12; t++) {
        int col = t * 8 + kq * 2;
        float2 bv = *(const float2*)(b + col);
        float2 p0 = *(const float2*)(P0 + col), q0 = *(const float2*)(Q0 + col);
        *(float2*)(o0 + col) = make_float2(acc[t].x + p0.x + q0.x + bv.x,
                                           acc[t].y + p0.y + q0.y + bv.y);
        float2 p1 = *(const float2*)(P1 + col), q1 = *(const float2*)(Q1 + col);
        *(float2*)(o1 + col) = make_float2(acc[t].z + p1.x + q1.x + bv.x,
                                           acc[t].w + p1.y + q1.y + bv.y);
    }
}

// ---------------------------------------------------------------------------
extern "C" void kernel_launch(void* const* d_in, const int* in_sizes, int n_in,
                              void* d_out, int out_size) {
    const int*   change = (const int*)d_in[0];
    const int*   is_sup = (const int*)d_in[1];
    const int*   tails  = (const int*)d_in[3];
    const float* x      = (const float*)d_in[4];
    const int*   ei     = (const int*)d_in[5];
    const float* attr   = (const float*)d_in[6];
    const float* mask   = (const float*)d_in[7];
    const float* stail  = (const float*)d_in[9];
    const float* W      = (const float*)d_in[10];
    const float* b      = (const float*)d_in[11];

    float* node_out = (float*)d_out;
    float* edge_out = node_out + (size_t)NN * NRD;

    init_k    <<<(NN * 24 + 255) / 256, 256>>>(x, node_out, W);
    scatter_k <<<(EE * 24 + 255) / 256, 256>>>(ei, attr, mask);
    finalize_k<<<(NN * 24 + 255) / 256, 256>>>(node_out);
    blend_k   <<<1, 1024>>>(change, is_sup, tails, stail, node_out);
    pq_mma    <<<(NN + 63) / 64, 256>>>(node_out);
    edge_mma  <<<EE / 128, 256>>>(attr, b, ei, edge_out);
}

// round 12
// speedup vs baseline: 1.1664x; 1.0208x over previous
#include <cuda_runtime.h>
#include <cuda_bf16.h>
#include <cstdint>

#define NN  100000
#define EE  800000
#define DD  96
#define NRD 102   // D + XD

// ---- scratch (device globals; no allocation allowed) ----
__device__ __align__(16) float4 g_num4[NN * 24];
__device__ float  g_den[NN];
__device__ __align__(16) float g_P[NN * DD];
__device__ __align__(16) float g_Q[NN * DD];
__device__ __align__(16) uint4 g_W3hi[96 * 12];     // bf16 [96 o][96 k]
__device__ __align__(16) uint4 g_W3lo[96 * 12];
__device__ __align__(16) uint4 g_W12hi[192 * 16];   // bf16 [192 n][128 k pad]
__device__ __align__(16) uint4 g_W12lo[192 * 16];

__device__ __forceinline__ uint32_t smem_u32(const void* p) {
    uint32_t a;
    asm("{ .reg .u64 t; cvta.to.shared.u64 t, %1; cvt.u32.u64 %0, t; }" : "=r"(a) : "l"(p));
    return a;
}

// ---------------------------------------------------------------------------
// bf16 split helpers
// ---------------------------------------------------------------------------
__device__ __forceinline__ void split4(float4 v, uint2& hi, uint2& lo) {
    uint32_t h01, h23, l01, l23;
    asm("cvt.rn.bf16x2.f32 %0, %1, %2;" : "=r"(h01) : "f"(v.y), "f"(v.x));
    asm("cvt.rn.bf16x2.f32 %0, %1, %2;" : "=r"(h23) : "f"(v.w), "f"(v.z));
    float r0 = v.x - __uint_as_float(h01 << 16);
    float r1 = v.y - __uint_as_float(h01 & 0xFFFF0000u);
    float r2 = v.z - __uint_as_float(h23 << 16);
    float r3 = v.w - __uint_as_float(h23 & 0xFFFF0000u);
    asm("cvt.rn.bf16x2.f32 %0, %1, %2;" : "=r"(l01) : "f"(r1), "f"(r0));
    asm("cvt.rn.bf16x2.f32 %0, %1, %2;" : "=r"(l23) : "f"(r3), "f"(r2));
    hi = make_uint2(h01, h23); lo = make_uint2(l01, l23);
}
__device__ __forceinline__ void split2(float f0, float f1, uint32_t& hi, uint32_t& lo) {
    asm("cvt.rn.bf16x2.f32 %0, %1, %2;" : "=r"(hi) : "f"(f1), "f"(f0));
    float r0 = f0 - __uint_as_float(hi << 16);
    float r1 = f1 - __uint_as_float(hi & 0xFFFF0000u);
    asm("cvt.rn.bf16x2.f32 %0, %1, %2;" : "=r"(lo) : "f"(r1), "f"(r0));
}

// ---------------------------------------------------------------------------
// K0: zero accumulators, write x cols; block 0 pre-splits W3 and W1|W2
// ---------------------------------------------------------------------------
__global__ void init_k(const float* __restrict__ x, float* __restrict__ node_out,
                       const float* __restrict__ W) {
    if (blockIdx.x == 0) {
        for (int i = threadIdx.x; i < 96 * 24; i += 256) {
            int o = i / 24, q = i % 24;
            float4 v = *(const float4*)(W + o * 300 + 204 + q * 4);
            uint2 hi, lo;
            split4(v, hi, lo);
            *((uint2*)g_W3hi + o * 24 + q) = hi;
            *((uint2*)g_W3lo + o * 24 + q) = lo;
        }
        for (int i = threadIdx.x; i < 192 * 64; i += 256) {
            int n = i >> 6, kp = i & 63, k = kp * 2;
            const float* src = (n < 96) ? (W + n * 300 + k) : (W + (n - 96) * 300 + 102 + k);
            float f0 = (k < 102) ? src[0] : 0.f;
            float f1 = (k + 1 < 102) ? src[1] : 0.f;
            uint32_t hi, lo;
            split2(f0, f1, hi, lo);
            ((uint32_t*)g_W12hi)[i] = hi;
            ((uint32_t*)g_W12lo)[i] = lo;
        }
    }
    int i = blockIdx.x * 256 + threadIdx.x;
    if (i < NN * 24) g_num4[i] = make_float4(0.f, 0.f, 0.f, 0.f);
    if (i < NN)      g_den[i] = 0.f;
    if (i < NN * 6)  node_out[(i / 6) * NRD + 96 + (i % 6)] = x[i];
}

// ---------------------------------------------------------------------------
// K1: masked scatter-sum — R8 proven form: one thread per (edge, quad)
// ---------------------------------------------------------------------------
__global__ void scatter_k(const int* __restrict__ ei,
                          const float* __restrict__ attr,
                          const float* __restrict__ mask) {
    int i = blockIdx.x * 256 + threadIdx.x;
    if (i >= EE * 24) return;
    int e = i / 24;
    int q = i - e * 24;
    int c = ei[EE + e];
    float m = mask[e];
    float4 v = *(const float4*)(attr + (size_t)e * 96 + q * 4);
    float* dst = ((float*)g_num4) + (size_t)c * 96 + q * 4;
    asm volatile("red.global.add.v4.f32 [%0], {%1,%2,%3,%4};"
                 :: "l"(dst), "f"(v.x * m), "f"(v.y * m), "f"(v.z * m), "f"(v.w * m)
                 : "memory");
    if (q == 0) atomicAdd(&g_den[c], m);
}

// ---------------------------------------------------------------------------
__global__ void finalize_k(float* __restrict__ node_out) {
    int i = blockIdx.x * 256 + threadIdx.x;
    if (i >= NN * 24) return;
    int n = i / 24;
    int q = i - n * 24;
    float inv = 1.f / (g_den[n] + 1.f);
    float4 v = g_num4[i];
    float* dst = node_out + (size_t)n * NRD + q * 4;
    dst[0] = v.x * inv; dst[1] = v.y * inv; dst[2] = v.z * inv; dst[3] = v.w * inv;
}

// ---------------------------------------------------------------------------
// K3: tail-row blend — parallel over 13 blocks (non-support path), dedup by
//     first-occurrence so each (node,dim) cell is written by exactly one thread.
// ---------------------------------------------------------------------------
__global__ void blend_k(const int* __restrict__ change,
                        const int* __restrict__ is_support,
                        const int* __restrict__ tails,
                        const float* __restrict__ support_tail,
                        float* __restrict__ node_out) {
    if (change[0] == 0) return;
    if (is_support[0]) {
        if (blockIdx.x != 0) return;
        const int TOT = 128 * NRD;
        int tid = threadIdx.x;
        float vals[13];
        int   addr[13];
        short dim[13];
        int cnt = 0;
        for (int i = tid; i < TOT; i += 1024) {
            int t = i / NRD, d = i - t * NRD;
            int node = tails[t];
            addr[cnt] = node * NRD + d;
            dim[cnt]  = (short)d;
            vals[cnt] = node_out[addr[cnt]];
            cnt++;
        }
        __shared__ float ssum[NRD];
        for (int d = tid; d < NRD; d += 1024) ssum[d] = 0.f;
        __syncthreads();
        for (int j = 0; j < cnt; j++) atomicAdd(&ssum[dim[j]], vals[j]);
        __syncthreads();
        for (int j = 0; j < cnt; j++)
            node_out[addr[j]] = ssum[dim[j]] * (1.f / 128.f);
    } else {
        int gtid = blockIdx.x * 1024 + threadIdx.x;
        if (gtid >= 128 * NRD) return;
        int t = gtid / NRD, d = gtid - t * NRD;
        int node = tails[t];
        bool first = true;
        for (int j = 0; j < t; j++)
            if (tails[j] == node) { first = false; break; }
        if (first) {
            int a = node * NRD + d;
            node_out[a] = 0.1f * support_tail[d] + 0.9f * node_out[a];
        }
    }
}

// ---------------------------------------------------------------------------
// shared MMA helpers
// ---------------------------------------------------------------------------
__device__ __forceinline__ void ldsm4(uint32_t addr, uint32_t* r) {
    asm volatile("ldmatrix.sync.aligned.m8n8.x4.shared.b16 {%0,%1,%2,%3}, [%4];"
                 : "=r"(r[0]), "=r"(r[1]), "=r"(r[2]), "=r"(r[3]) : "r"(addr));
}
__device__ __forceinline__ void mma_bf16(float4& c, const uint32_t* a,
                                         uint32_t b0, uint32_t b1) {
    asm volatile(
        "mma.sync.aligned.m16n8k16.row.col.f32.bf16.bf16.f32 "
        "{%0,%1,%2,%3}, {%4,%5,%6,%7}, {%8,%9}, {%0,%1,%2,%3};"
        : "+f"(c.x), "+f"(c.y), "+f"(c.z), "+f"(c.w)
        : "r"(a[0]), "r"(a[1]), "r"(a[2]), "r"(a[3]), "r"(b0), "r"(b1));
}

#define RS 80           // A row stride bytes (64B data + 16B pad)

// ---------------------------------------------------------------------------
// K4: P|Q fused GEMM via HMMA bf16 3-term split (R8 version, proven)
// ---------------------------------------------------------------------------
__global__ __launch_bounds__(256, 2) void pq_mma(const float* __restrict__ node_rep) {
    __shared__ __align__(16) char sAhi[64 * RS];
    __shared__ __align__(16) char sAlo[64 * RS];
    __shared__ __align__(16) char sBhi[192 * RS];
    __shared__ __align__(16) char sBlo[192 * RS];

    int tid = threadIdx.x, lane = tid & 31, w = tid >> 5;
    int n0 = blockIdx.x * 64;
    int w4 = w & 3, nh = w >> 2;

    uint32_t aHi = smem_u32(sAhi), aLo = smem_u32(sAlo);
    uint32_t bHi = smem_u32(sBhi), bLo = smem_u32(sBlo);

    uint32_t aoff = (uint32_t)(w4 * 16 + (lane & 15)) * RS + ((lane >> 4) & 1) * 16;
    uint32_t boff = ((lane >> 4) & 1) * 8 * RS + (uint32_t)(lane & 7) * RS
                  + ((lane >> 3) & 1) * 16;

    float4 acc[12];
    #pragma unroll
    for (int t = 0; t < 12; t++) acc[t] = make_float4(0.f, 0.f, 0.f, 0.f);

    #pragma unroll
    for (int c = 0; c < 4; c++) {
        int kc0 = c * 32;
        if (c) __syncthreads();
        #pragma unroll
        for (int v = 0; v < 4; v++) {
            int f = tid + v * 256;
            int r = f >> 4, j = f & 15;
            int k = kc0 + j * 2;
            int n = n0 + r;
            float2 val = (n < NN && k < 102)
                ? *(const float2*)(node_rep + (size_t)n * NRD + k)
                : make_float2(0.f, 0.f);
            uint32_t hi, lo;
            split2(val.x, val.y, hi, lo);
            int off = r * RS + j * 4;
            *(uint32_t*)(sAhi + off) = hi;
            *(uint32_t*)(sAlo + off) = lo;
        }
        #pragma unroll
        for (int v = 0; v < 6; v++) {
            int f = tid + v * 256;
            int sel = f >= 768;
            int g = sel ? f - 768 : f;
            int o = g >> 2, q = g & 3;
            uint4 val = (sel ? g_W12lo : g_W12hi)[o * 16 + c * 4 + q];
            *(uint4*)((sel ? sBlo : sBhi) + o * RS + q * 16) = val;
        }
        __syncthreads();

        #pragma unroll
        for (int kc16 = 0; kc16 < 2; kc16++) {
            uint32_t ah[4], al[4];
            ldsm4(aHi + aoff + kc16 * 32, ah);
            ldsm4(aLo + aoff + kc16 * 32, al);
            #pragma unroll
            for (int tp = 0; tp < 6; tp++) {
                uint32_t bh[4], bl[4];
                uint32_t bo = (uint32_t)(nh * 96 + tp * 16) * RS + boff + kc16 * 32;
                ldsm4(bHi + bo, bh);
                ldsm4(bLo + bo, bl);
                mma_bf16(acc[tp * 2],     ah, bh[0], bh[1]);
                mma_bf16(acc[tp * 2],     ah, bl[0], bl[1]);
                mma_bf16(acc[tp * 2],     al, bh[0], bh[1]);
                mma_bf16(acc[tp * 2 + 1], ah, bh[2], bh[3]);
                mma_bf16(acc[tp * 2 + 1], ah, bl[2], bl[3]);
                mma_bf16(acc[tp * 2 + 1], al, bh[2], bh[3]);
            }
        }
    }

    float* outb = nh ? g_Q : g_P;
    int mrow = w4 * 16 + (lane >> 2);
    int kq = lane & 3;
    int node0 = n0 + mrow, node1 = node0 + 8;
    #pragma unroll
    for (int t = 0; t < 12; t++) {
        int col = t * 8 + kq * 2;
        if (node0 < NN)
            *(float2*)(outb + (size_t)node0 * 96 + col) = make_float2(acc[t].x, acc[t].y);
        if (node1 < NN)
            *(float2*)(outb + (size_t)node1 * 96 + col) = make_float2(acc[t].z, acc[t].w);
    }
}

// ---------------------------------------------------------------------------
// K5: edge_rep HMMA — B resident (loaded once), A double-buffered, 1 sync/chunk.
//   dyn smem layout: Ahi0 Alo0 Ahi1 Alo1 (4 x 10240) | Bhi Blo (2 x 96*208)
// ---------------------------------------------------------------------------
#define RS2 208
#define SB_A(buf)  ((buf) * 20480)
#define SB_BHI 40960
#define SB_BLO (40960 + 96 * RS2)
#define SB_TOT (40960 + 2 * 96 * RS2)     // 80896 B

__global__ __launch_bounds__(256, 2) void edge_mma(const float* __restrict__ attr,
                                                   const float* __restrict__ b,
                                                   const int* __restrict__ ei,
                                                   float* __restrict__ out) {
    extern __shared__ __align__(16) char smem[];
    int tid = threadIdx.x, lane = tid & 31, w = tid >> 5;
    size_t e0 = (size_t)blockIdx.x * 128;

    // hoisted epilogue indices + L1 prefetch of P/Q rows
    int mrow = w * 16 + (lane >> 2);
    int kq = lane & 3;
    int er0 = (int)e0 + mrow;
    int er1 = er0 + 8;
    int r0i = ei[er0], c0i = ei[EE + er0];
    int r1i = ei[er1], c1i = ei[EE + er1];
    if (kq < 3) {
        int lo = kq * 32;
        asm volatile("prefetch.global.L1 [%0];" :: "l"(g_P + (size_t)r0i * 96 + lo));
        asm volatile("prefetch.global.L1 [%0];" :: "l"(g_Q + (size_t)c0i * 96 + lo));
        asm volatile("prefetch.global.L1 [%0];" :: "l"(g_P + (size_t)r1i * 96 + lo));
        asm volatile("prefetch.global.L1 [%0];" :: "l"(g_Q + (size_t)c1i * 96 + lo));
    }

    uint32_t sb = smem_u32(smem);

    uint32_t aoff = (uint32_t)(w * 16 + (lane & 15)) * RS + ((lane >> 4) & 1) * 16;
    uint32_t boff = ((lane >> 4) & 1) * 8 * RS2 + (uint32_t)(lane & 7) * RS2
                  + ((lane >> 3) & 1) * 16;

    // ---- load full W3 (hi/lo) once: 2 x 96 rows x 12 uint4 = 2304 ----
    #pragma unroll
    for (int v = 0; v < 9; v++) {
        int f = tid + v * 256;
        int sel = f >= 1152;
        int g = sel ? f - 1152 : f;
        int o = g / 12, q = g % 12;
        uint4 val = (sel ? g_W3lo : g_W3hi)[o * 12 + q];
        *(uint4*)(smem + (sel ? SB_BLO : SB_BHI) + o * RS2 + q * 16) = val;
    }

    float4 acc[12];
    #pragma unroll
    for (int t = 0; t < 12; t++) acc[t] = make_float4(0.f, 0.f, 0.f, 0.f);

    float4 pa[4];
    // prefetch + store chunk 0 into buf 0
    #pragma unroll
    for (int v = 0; v < 4; v++) {
        int f = tid + v * 256;
        int r = f >> 3, q4 = f & 7;
        pa[v] = *(const float4*)(attr + (e0 + r) * 96 + q4 * 4);
    }
    #pragma unroll
    for (int v = 0; v < 4; v++) {
        int f = tid + v * 256;
        int r = f >> 3, q4 = f & 7;
        uint2 hi, lo;
        split4(pa[v], hi, lo);
        int off = SB_A(0) + r * RS + q4 * 8;
        *(uint2*)(smem + off) = hi;
        *(uint2*)(smem + off + 10240) = lo;
    }
    __syncthreads();

    #pragma unroll
    for (int c = 0; c < 3; c++) {
        // prefetch next chunk (latency covered by this chunk's MMAs)
        if (c < 2) {
            int kc0 = (c + 1) * 32;
            #pragma unroll
            for (int v = 0; v < 4; v++) {
                int f = tid + v * 256;
                int r = f >> 3, q4 = f & 7;
                pa[v] = *(const float4*)(attr + (e0 + r) * 96 + kc0 + q4 * 4);
            }
        }
        uint32_t abase = sb + SB_A(c & 1);
        #pragma unroll
        for (int kc16 = 0; kc16 < 2; kc16++) {
            uint32_t ah[4], al[4];
            ldsm4(abase + aoff + kc16 * 32, ah);
            ldsm4(abase + 10240 + aoff + kc16 * 32, al);
            uint32_t kbyte = (uint32_t)c * 64 + kc16 * 32;
            #pragma unroll
            for (int tp = 0; tp < 6; tp++) {
                uint32_t bh[4], bl[4];
                uint32_t bo = (uint32_t)(tp * 16) * RS2 + boff + kbyte;
                ldsm4(sb + SB_BHI + bo, bh);
                ldsm4(sb + SB_BLO + bo, bl);
                mma_bf16(acc[tp * 2],     ah, bh[0], bh[1]);
                mma_bf16(acc[tp * 2],     ah, bl[0], bl[1]);
                mma_bf16(acc[tp * 2],     al, bh[0], bh[1]);
                mma_bf16(acc[tp * 2 + 1], ah, bh[2], bh[3]);
                mma_bf16(acc[tp * 2 + 1], ah, bl[2], bl[3]);
                mma_bf16(acc[tp * 2 + 1], al, bh[2], bh[3]);
            }
        }
        // store prefetched chunk into the other buffer (its readers synced at c-1)
        if (c < 2) {
            int dstb = SB_A((c + 1) & 1);
            #pragma unroll
            for (int v = 0; v < 4; v++) {
                int f = tid + v * 256;
                int r = f >> 3, q4 = f & 7;
                uint2 hi, lo;
                split4(pa[v], hi, lo);
                int off = dstb + r * RS + q4 * 8;
                *(uint2*)(smem + off) = hi;
                *(uint2*)(smem + off + 10240) = lo;
            }
            __syncthreads();
        }
    }

    // epilogue (direct form, indices already in registers)
    const float* P0 = g_P + (size_t)r0i * 96;
    const float* Q0 = g_Q + (size_t)c0i * 96;
    const float* P1 = g_P + (size_t)r1i * 96;
    const float* Q1 = g_Q + (size_t)c1i * 96;
    float* o0 = out + (size_t)er0 * 96;
    float* o1 = out + (size_t)er1 * 96;
    #pragma unroll
    for (int t = 0; t < 12; t++) {
        int col = t * 8 + kq * 2;
        float2 bv = *(const float2*)(b + col);
        float2 p0 = *(const float2*)(P0 + col), q0 = *(const float2*)(Q0 + col);
        *(float2*)(o0 + col) = make_float2(acc[t].x + p0.x + q0.x + bv.x,
                                           acc[t].y + p0.y + q0.y + bv.y);
        float2 p1 = *(const float2*)(P1 + col), q1 = *(const float2*)(Q1 + col);
        *(float2*)(o1 + col) = make_float2(acc[t].z + p1.x + q1.x + bv.x,
                                           acc[t].w + p1.y + q1.y + bv.y);
    }
}

// ---------------------------------------------------------------------------
extern "C" void kernel_launch(void* const* d_in, const int* in_sizes, int n_in,
                              void* d_out, int out_size) {
    const int*   change = (const int*)d_in[0];
    const int*   is_sup = (const int*)d_in[1];
    const int*   tails  = (const int*)d_in[3];
    const float* x      = (const float*)d_in[4];
    const int*   ei     = (const int*)d_in[5];
    const float* attr   = (const float*)d_in[6];
    const float* mask   = (const float*)d_in[7];
    const float* stail  = (const float*)d_in[9];
    const float* W      = (const float*)d_in[10];
    const float* b      = (const float*)d_in[11];

    float* node_out = (float*)d_out;
    float* edge_out = node_out + (size_t)NN * NRD;

    cudaFuncSetAttribute(edge_mma, cudaFuncAttributeMaxDynamicSharedMemorySize, SB_TOT);

    init_k    <<<(NN * 24 + 255) / 256, 256>>>(x, node_out, W);
    scatter_k <<<(EE * 24 + 255) / 256, 256>>>(ei, attr, mask);
    finalize_k<<<(NN * 24 + 255) / 256, 256>>>(node_out);
    blend_k   <<<13, 1024>>>(change, is_sup, tails, stail, node_out);
    pq_mma    <<<(NN + 63) / 64, 256>>>(node_out);
    edge_mma  <<<EE / 128, 256, SB_TOT>>>(attr, b, ei, edge_out);
}

// round 13
// speedup vs baseline: 1.2201x; 1.0461x over previous
#include <cuda_runtime.h>
#include <cuda_bf16.h>
#include <cstdint>

#define NN  100000
#define EE  800000
#define DD  96
#define NRD 102   // D + XD

// ---- scratch (device globals; no allocation allowed) ----
__device__ __align__(16) float4 g_num4[NN * 24];
__device__ float  g_den[NN];
__device__ int    g_tailflag[NN];
__device__ __align__(16) float g_P[NN * DD];
__device__ __align__(16) float g_Q[NN * DD];
__device__ __align__(16) uint4 g_W3hi[96 * 12];     // bf16 [96 o][96 k]
__device__ __align__(16) uint4 g_W3lo[96 * 12];
__device__ __align__(16) uint4 g_W12hi[192 * 16];   // bf16 [192 n][128 k pad]
__device__ __align__(16) uint4 g_W12lo[192 * 16];

__device__ __forceinline__ uint32_t smem_u32(const void* p) {
    uint32_t a;
    asm("{ .reg .u64 t; cvta.to.shared.u64 t, %1; cvt.u32.u64 %0, t; }" : "=r"(a) : "l"(p));
    return a;
}

// ---------------------------------------------------------------------------
// bf16 split helpers
// ---------------------------------------------------------------------------
__device__ __forceinline__ void split4(float4 v, uint2& hi, uint2& lo) {
    uint32_t h01, h23, l01, l23;
    asm("cvt.rn.bf16x2.f32 %0, %1, %2;" : "=r"(h01) : "f"(v.y), "f"(v.x));
    asm("cvt.rn.bf16x2.f32 %0, %1, %2;" : "=r"(h23) : "f"(v.w), "f"(v.z));
    float r0 = v.x - __uint_as_float(h01 << 16);
    float r1 = v.y - __uint_as_float(h01 & 0xFFFF0000u);
    float r2 = v.z - __uint_as_float(h23 << 16);
    float r3 = v.w - __uint_as_float(h23 & 0xFFFF0000u);
    asm("cvt.rn.bf16x2.f32 %0, %1, %2;" : "=r"(l01) : "f"(r1), "f"(r0));
    asm("cvt.rn.bf16x2.f32 %0, %1, %2;" : "=r"(l23) : "f"(r3), "f"(r2));
    hi = make_uint2(h01, h23); lo = make_uint2(l01, l23);
}
__device__ __forceinline__ void split2(float f0, float f1, uint32_t& hi, uint32_t& lo) {
    asm("cvt.rn.bf16x2.f32 %0, %1, %2;" : "=r"(hi) : "f"(f1), "f"(f0));
    float r0 = f0 - __uint_as_float(hi << 16);
    float r1 = f1 - __uint_as_float(hi & 0xFFFF0000u);
    asm("cvt.rn.bf16x2.f32 %0, %1, %2;" : "=r"(lo) : "f"(r1), "f"(r0));
}

// ---------------------------------------------------------------------------
// K0: zero accumulators + tail flags; block 0 pre-splits W3 and W1|W2
// ---------------------------------------------------------------------------
__global__ void init_k(const float* __restrict__ W) {
    if (blockIdx.x == 0) {
        for (int i = threadIdx.x; i < 96 * 24; i += 256) {
            int o = i / 24, q = i % 24;
            float4 v = *(const float4*)(W + o * 300 + 204 + q * 4);
            uint2 hi, lo;
            split4(v, hi, lo);
            *((uint2*)g_W3hi + o * 24 + q) = hi;
            *((uint2*)g_W3lo + o * 24 + q) = lo;
        }
        for (int i = threadIdx.x; i < 192 * 64; i += 256) {
            int n = i >> 6, kp = i & 63, k = kp * 2;
            const float* src = (n < 96) ? (W + n * 300 + k) : (W + (n - 96) * 300 + 102 + k);
            float f0 = (k < 102) ? src[0] : 0.f;
            float f1 = (k + 1 < 102) ? src[1] : 0.f;
            uint32_t hi, lo;
            split2(f0, f1, hi, lo);
            ((uint32_t*)g_W12hi)[i] = hi;
            ((uint32_t*)g_W12lo)[i] = lo;
        }
    }
    int i = blockIdx.x * 256 + threadIdx.x;
    if (i < NN * 24) g_num4[i] = make_float4(0.f, 0.f, 0.f, 0.f);
    if (i < NN)      { g_den[i] = 0.f; g_tailflag[i] = 0; }
}

// ---------------------------------------------------------------------------
// K1: masked scatter-sum (proven); block 0 also sets tail flags
// ---------------------------------------------------------------------------
__global__ void scatter_k(const int* __restrict__ ei,
                          const float* __restrict__ attr,
                          const float* __restrict__ mask,
                          const int* __restrict__ tails) {
    if (blockIdx.x == 0 && threadIdx.x < 128)
        g_tailflag[tails[threadIdx.x]] = 1;
    int i = blockIdx.x * 256 + threadIdx.x;
    if (i >= EE * 24) return;
    int e = i / 24;
    int q = i - e * 24;
    int c = ei[EE + e];
    float m = mask[e];
    float4 v = *(const float4*)(attr + (size_t)e * 96 + q * 4);
    float* dst = ((float*)g_num4) + (size_t)c * 96 + q * 4;
    asm volatile("red.global.add.v4.f32 [%0], {%1,%2,%3,%4};"
                 :: "l"(dst), "f"(v.x * m), "f"(v.y * m), "f"(v.z * m), "f"(v.w * m)
                 : "memory");
    if (q == 0) atomicAdd(&g_den[c], m);
}

// ---------------------------------------------------------------------------
// K2: finalize — num/(den+1) for cols 0..95, x for cols 96..101, with the
//     non-support tail blend fused in (flag set by scatter block 0).
// ---------------------------------------------------------------------------
__global__ void finalize_k(const float* __restrict__ x,
                           float* __restrict__ node_out,
                           const int* __restrict__ change,
                           const int* __restrict__ is_support,
                           const float* __restrict__ stail) {
    int i = blockIdx.x * 256 + threadIdx.x;
    if (i >= NN * 26) return;
    int n = i / 26;
    int q = i - n * 26;
    bool bl = g_tailflag[n] && change[0] && !is_support[0];
    if (q < 24) {
        float inv = 1.f / (g_den[n] + 1.f);
        float4 v = g_num4[n * 24 + q];
        float o0 = v.x * inv, o1 = v.y * inv, o2 = v.z * inv, o3 = v.w * inv;
        int col = q * 4;
        if (bl) {
            o0 = 0.1f * stail[col]     + 0.9f * o0;
            o1 = 0.1f * stail[col + 1] + 0.9f * o1;
            o2 = 0.1f * stail[col + 2] + 0.9f * o2;
            o3 = 0.1f * stail[col + 3] + 0.9f * o3;
        }
        float* dst = node_out + (size_t)n * NRD + col;
        dst[0] = o0; dst[1] = o1; dst[2] = o2; dst[3] = o3;
    } else {
        int j0 = (q - 24) * 3;                      // 0 or 3
        #pragma unroll
        for (int j = 0; j < 3; j++) {
            int d = 96 + j0 + j;
            float o = x[(size_t)n * 6 + j0 + j];
            if (bl) o = 0.1f * stail[d] + 0.9f * o;
            node_out[(size_t)n * NRD + d] = o;
        }
    }
}

// ---------------------------------------------------------------------------
// K3: tail-row blend — SUPPORT PATH ONLY (mean over tails); early-exit else.
// ---------------------------------------------------------------------------
__global__ void blend_k(const int* __restrict__ change,
                        const int* __restrict__ is_support,
                        const int* __restrict__ tails,
                        float* __restrict__ node_out) {
    if (change[0] == 0 || is_support[0] == 0) return;
    const int TOT = 128 * NRD;
    int tid = threadIdx.x;
    float vals[13];
    int   addr[13];
    short dim[13];
    int cnt = 0;
    for (int i = tid; i < TOT; i += 1024) {
        int t = i / NRD, d = i - t * NRD;
        int node = tails[t];
        addr[cnt] = node * NRD + d;
        dim[cnt]  = (short)d;
        vals[cnt] = node_out[addr[cnt]];
        cnt++;
    }
    __shared__ float ssum[NRD];
    for (int d = tid; d < NRD; d += 1024) ssum[d] = 0.f;
    __syncthreads();
    for (int j = 0; j < cnt; j++) atomicAdd(&ssum[dim[j]], vals[j]);
    __syncthreads();
    for (int j = 0; j < cnt; j++)
        node_out[addr[j]] = ssum[dim[j]] * (1.f / 128.f);
}

// ---------------------------------------------------------------------------
// shared MMA helpers
// ---------------------------------------------------------------------------
__device__ __forceinline__ void ldsm4(uint32_t addr, uint32_t* r) {
    asm volatile("ldmatrix.sync.aligned.m8n8.x4.shared.b16 {%0,%1,%2,%3}, [%4];"
                 : "=r"(r[0]), "=r"(r[1]), "=r"(r[2]), "=r"(r[3]) : "r"(addr));
}
__device__ __forceinline__ void mma_bf16(float4& c, const uint32_t* a,
                                         uint32_t b0, uint32_t b1) {
    asm volatile(
        "mma.sync.aligned.m16n8k16.row.col.f32.bf16.bf16.f32 "
        "{%0,%1,%2,%3}, {%4,%5,%6,%7}, {%8,%9}, {%0,%1,%2,%3};"
        : "+f"(c.x), "+f"(c.y), "+f"(c.z), "+f"(c.w)
        : "r"(a[0]), "r"(a[1]), "r"(a[2]), "r"(a[3]), "r"(b0), "r"(b1));
}

#define RS 80           // A row stride bytes (64B data + 16B pad)

// ---------------------------------------------------------------------------
// K4: P|Q fused GEMM via HMMA bf16 3-term split (proven R8 version)
// ---------------------------------------------------------------------------
__global__ __launch_bounds__(256, 2) void pq_mma(const float* __restrict__ node_rep) {
    __shared__ __align__(16) char sAhi[64 * RS];
    __shared__ __align__(16) char sAlo[64 * RS];
    __shared__ __align__(16) char sBhi[192 * RS];
    __shared__ __align__(16) char sBlo[192 * RS];

    int tid = threadIdx.x, lane = tid & 31, w = tid >> 5;
    int n0 = blockIdx.x * 64;
    int w4 = w & 3, nh = w >> 2;

    uint32_t aHi = smem_u32(sAhi), aLo = smem_u32(sAlo);
    uint32_t bHi = smem_u32(sBhi), bLo = smem_u32(sBlo);

    uint32_t aoff = (uint32_t)(w4 * 16 + (lane & 15)) * RS + ((lane >> 4) & 1) * 16;
    uint32_t boff = ((lane >> 4) & 1) * 8 * RS + (uint32_t)(lane & 7) * RS
                  + ((lane >> 3) & 1) * 16;

    float4 acc[12];
    #pragma unroll
    for (int t = 0; t < 12; t++) acc[t] = make_float4(0.f, 0.f, 0.f, 0.f);

    #pragma unroll
    for (int c = 0; c < 4; c++) {
        int kc0 = c * 32;
        if (c) __syncthreads();
        #pragma unroll
        for (int v = 0; v < 4; v++) {
            int f = tid + v * 256;
            int r = f >> 4, j = f & 15;
            int k = kc0 + j * 2;
            int n = n0 + r;
            float2 val = (n < NN && k < 102)
                ? *(const float2*)(node_rep + (size_t)n * NRD + k)
                : make_float2(0.f, 0.f);
            uint32_t hi, lo;
            split2(val.x, val.y, hi, lo);
            int off = r * RS + j * 4;
            *(uint32_t*)(sAhi + off) = hi;
            *(uint32_t*)(sAlo + off) = lo;
        }
        #pragma unroll
        for (int v = 0; v < 6; v++) {
            int f = tid + v * 256;
            int sel = f >= 768;
            int g = sel ? f - 768 : f;
            int o = g >> 2, q = g & 3;
            uint4 val = (sel ? g_W12lo : g_W12hi)[o * 16 + c * 4 + q];
            *(uint4*)((sel ? sBlo : sBhi) + o * RS + q * 16) = val;
        }
        __syncthreads();

        #pragma unroll
        for (int kc16 = 0; kc16 < 2; kc16++) {
            uint32_t ah[4], al[4];
            ldsm4(aHi + aoff + kc16 * 32, ah);
            ldsm4(aLo + aoff + kc16 * 32, al);
            #pragma unroll
            for (int tp = 0; tp < 6; tp++) {
                uint32_t bh[4], bl[4];
                uint32_t bo = (uint32_t)(nh * 96 + tp * 16) * RS + boff + kc16 * 32;
                ldsm4(bHi + bo, bh);
                ldsm4(bLo + bo, bl);
                mma_bf16(acc[tp * 2],     ah, bh[0], bh[1]);
                mma_bf16(acc[tp * 2],     ah, bl[0], bl[1]);
                mma_bf16(acc[tp * 2],     al, bh[0], bh[1]);
                mma_bf16(acc[tp * 2 + 1], ah, bh[2], bh[3]);
                mma_bf16(acc[tp * 2 + 1], ah, bl[2], bl[3]);
                mma_bf16(acc[tp * 2 + 1], al, bh[2], bh[3]);
            }
        }
    }

    float* outb = nh ? g_Q : g_P;
    int mrow = w4 * 16 + (lane >> 2);
    int kq = lane & 3;
    int node0 = n0 + mrow, node1 = node0 + 8;
    #pragma unroll
    for (int t = 0; t < 12; t++) {
        int col = t * 8 + kq * 2;
        if (node0 < NN)
            *(float2*)(outb + (size_t)node0 * 96 + col) = make_float2(acc[t].x, acc[t].y);
        if (node1 < NN)
            *(float2*)(outb + (size_t)node1 * 96 + col) = make_float2(acc[t].z, acc[t].w);
    }
}

// ---------------------------------------------------------------------------
// K5: edge_rep HMMA — B resident, single A buffer (60.4KB smem), 3 CTAs/SM.
//   dyn smem: Ahi [0,10240) Alo [10240,20480) | Bhi Blo (2 x 96*208)
// ---------------------------------------------------------------------------
#define RS2 208
#define SB_AHI 0
#define SB_ALO 10240
#define SB_BHI 20480
#define SB_BLO (20480 + 96 * RS2)
#define SB_TOT (20480 + 2 * 96 * RS2)     // 60416 B

__global__ __launch_bounds__(256, 3) void edge_mma(const float* __restrict__ attr,
                                                   const float* __restrict__ b,
                                                   const int* __restrict__ ei,
                                                   float* __restrict__ out) {
    extern __shared__ __align__(16) char smem[];
    int tid = threadIdx.x, lane = tid & 31, w = tid >> 5;
    size_t e0 = (size_t)blockIdx.x * 128;

    uint32_t sb = smem_u32(smem);

    uint32_t aoff = (uint32_t)(w * 16 + (lane & 15)) * RS + ((lane >> 4) & 1) * 16;
    uint32_t boff = ((lane >> 4) & 1) * 8 * RS2 + (uint32_t)(lane & 7) * RS2
                  + ((lane >> 3) & 1) * 16;

    // ---- load full W3 (hi/lo) once ----
    #pragma unroll
    for (int v = 0; v < 9; v++) {
        int f = tid + v * 256;
        int sel = f >= 1152;
        int g = sel ? f - 1152 : f;
        int o = g / 12, q = g % 12;
        uint4 val = (sel ? g_W3lo : g_W3hi)[o * 12 + q];
        *(uint4*)(smem + (sel ? SB_BLO : SB_BHI) + o * RS2 + q * 16) = val;
    }

    float4 acc[12];
    #pragma unroll
    for (int t = 0; t < 12; t++) acc[t] = make_float4(0.f, 0.f, 0.f, 0.f);

    float4 pa[4];
    #pragma unroll
    for (int v = 0; v < 4; v++) {
        int f = tid + v * 256;
        int r = f >> 3, q4 = f & 7;
        pa[v] = *(const float4*)(attr + (e0 + r) * 96 + q4 * 4);
    }

    #pragma unroll
    for (int c = 0; c < 3; c++) {
        if (c) __syncthreads();                 // prev chunk's MMA reads done
        #pragma unroll
        for (int v = 0; v < 4; v++) {
            int f = tid + v * 256;
            int r = f >> 3, q4 = f & 7;
            uint2 hi, lo;
            split4(pa[v], hi, lo);
            int off = r * RS + q4 * 8;
            *(uint2*)(smem + SB_AHI + off) = hi;
            *(uint2*)(smem + SB_ALO + off) = lo;
        }
        __syncthreads();
        if (c < 2) {
            int kc0 = (c + 1) * 32;
            #pragma unroll
            for (int v = 0; v < 4; v++) {
                int f = tid + v * 256;
                int r = f >> 3, q4 = f & 7;
                pa[v] = *(const float4*)(attr + (e0 + r) * 96 + kc0 + q4 * 4);
            }
        }
        #pragma unroll
        for (int kc16 = 0; kc16 < 2; kc16++) {
            uint32_t ah[4], al[4];
            ldsm4(sb + SB_AHI + aoff + kc16 * 32, ah);
            ldsm4(sb + SB_ALO + aoff + kc16 * 32, al);
            uint32_t kbyte = (uint32_t)c * 64 + kc16 * 32;
            #pragma unroll
            for (int tp = 0; tp < 6; tp++) {
                uint32_t bh[4], bl[4];
                uint32_t bo = (uint32_t)(tp * 16) * RS2 + boff + kbyte;
                ldsm4(sb + SB_BHI + bo, bh);
                ldsm4(sb + SB_BLO + bo, bl);
                mma_bf16(acc[tp * 2],     ah, bh[0], bh[1]);
                mma_bf16(acc[tp * 2],     ah, bl[0], bl[1]);
                mma_bf16(acc[tp * 2],     al, bh[0], bh[1]);
                mma_bf16(acc[tp * 2 + 1], ah, bh[2], bh[3]);
                mma_bf16(acc[tp * 2 + 1], ah, bl[2], bl[3]);
                mma_bf16(acc[tp * 2 + 1], al, bh[2], bh[3]);
            }
        }
    }

    // epilogue (indices loaded here to keep main-loop registers low)
    int mrow = w * 16 + (lane >> 2);
    int kq = lane & 3;
    int er0 = (int)e0 + mrow;
    int er1 = er0 + 8;
    int r0i = ei[er0], c0i = ei[EE + er0];
    int r1i = ei[er1], c1i = ei[EE + er1];
    const float* P0 = g_P + (size_t)r0i * 96;
    const float* Q0 = g_Q + (size_t)c0i * 96;
    const float* P1 = g_P + (size_t)r1i * 96;
    const float* Q1 = g_Q + (size_t)c1i * 96;
    float* o0 = out + (size_t)er0 * 96;
    float* o1 = out + (size_t)er1 * 96;
    #pragma unroll
    for (int t = 0; t < 12; t++) {
        int col = t * 8 + kq * 2;
        float2 bv = *(const float2*)(b + col);
        float2 p0 = *(const float2*)(P0 + col), q0 = *(const float2*)(Q0 + col);
        *(float2*)(o0 + col) = make_float2(acc[t].x + p0.x + q0.x + bv.x,
                                           acc[t].y + p0.y + q0.y + bv.y);
        float2 p1 = *(const float2*)(P1 + col), q1 = *(const float2*)(Q1 + col);
        *(float2*)(o1 + col) = make_float2(acc[t].z + p1.x + q1.x + bv.x,
                                           acc[t].w + p1.y + q1.y + bv.y);
    }
}

// ---------------------------------------------------------------------------
extern "C" void kernel_launch(void* const* d_in, const int* in_sizes, int n_in,
                              void* d_out, int out_size) {
    const int*   change = (const int*)d_in[0];
    const int*   is_sup = (const int*)d_in[1];
    const int*   tails  = (const int*)d_in[3];
    const float* x      = (const float*)d_in[4];
    const int*   ei     = (const int*)d_in[5];
    const float* attr   = (const float*)d_in[6];
    const float* mask   = (const float*)d_in[7];
    const float* stail  = (const float*)d_in[9];
    const float* W      = (const float*)d_in[10];
    const float* b      = (const float*)d_in[11];

    float* node_out = (float*)d_out;
    float* edge_out = node_out + (size_t)NN * NRD;

    cudaFuncSetAttribute(edge_mma, cudaFuncAttributeMaxDynamicSharedMemorySize, SB_TOT);

    init_k    <<<(NN * 24 + 255) / 256, 256>>>(W);
    scatter_k <<<(EE * 24 + 255) / 256, 256>>>(ei, attr, mask, tails);
    finalize_k<<<(NN * 26 + 255) / 256, 256>>>(x, node_out, change, is_sup, stail);
    blend_k   <<<1, 1024>>>(change, is_sup, tails, node_out);
    pq_mma    <<<(NN + 63) / 64, 256>>>(node_out);
    edge_mma  <<<EE / 128, 256, SB_TOT>>>(attr, b, ei, edge_out);
}